// round 5
// baseline (speedup 1.0000x reference)
#include <cuda_runtime.h>
#include <cstdint>

// loss = ALPHA*mean(G) + (1-ALPHA)*mse
//   mse     = sum_{t>0}(t-p)^2 / max(count,1)
//   mean(G) = (1/N) * 36-pixel corner term (double reflect-101 conv of the
//             zero-sum composed kernel collapses; wr = [-.75,-1,-.25,0..0,.25,1,.75])
//
// TMA streaming version: cp.async.bulk global->SMEM pipeline (5 stages x 4KB
// per array), consumers reduce from SMEM. Bypasses the per-warp L1tex request
// path that capped the LDG versions at ~4.1 TB/s.

#define ALPHA  0.2
#define H_DIM  4096
#define W_DIM  4096
#define GRID   296       // 148 SMs * 2 CTAs
#define NTHR   256
#define CHUNK  1024      // floats per chunk = 4KB
#define STAGES 5

__device__ float2       g_partials[GRID];
__device__ unsigned int g_ticket = 0;    // atomicInc wraps to 0 -> no init kernel

__device__ __forceinline__ uint32_t smem_u32(const void* p) {
    return (uint32_t)__cvta_generic_to_shared(p);
}

__device__ __forceinline__ void mbar_init(uint32_t mbar, uint32_t count) {
    asm volatile("mbarrier.init.shared.b64 [%0], %1;" :: "r"(mbar), "r"(count) : "memory");
}

__device__ __forceinline__ void mbar_expect_tx(uint32_t mbar, uint32_t bytes) {
    asm volatile("mbarrier.arrive.expect_tx.shared.b64 _, [%0], %1;"
                 :: "r"(mbar), "r"(bytes) : "memory");
}

__device__ __forceinline__ void bulk_ld(uint32_t dst_smem, const void* src, uint32_t bytes,
                                        uint32_t mbar) {
    asm volatile("cp.async.bulk.shared::cluster.global.mbarrier::complete_tx::bytes "
                 "[%0], [%1], %2, [%3];"
                 :: "r"(dst_smem), "l"(src), "r"(bytes), "r"(mbar) : "memory");
}

__device__ __forceinline__ void mbar_wait(uint32_t mbar, uint32_t phase) {
    asm volatile(
        "{\n\t"
        ".reg .pred P1;\n\t"
        "LAB_WAIT_%=:\n\t"
        "mbarrier.try_wait.parity.acquire.cta.shared::cta.b64 P1, [%0], %1, 0x989680;\n\t"
        "@P1 bra LAB_DONE_%=;\n\t"
        "bra LAB_WAIT_%=;\n\t"
        "LAB_DONE_%=:\n\t"
        "}"
        :: "r"(mbar), "r"(phase) : "memory");
}

__device__ __forceinline__ void acc4(const float4 t, const float4 p,
                                     float& s, float& c) {
    if (t.x > 0.0f) { float d = t.x - p.x; s = fmaf(d, d, s); c += 1.0f; }
    if (t.y > 0.0f) { float d = t.y - p.y; s = fmaf(d, d, s); c += 1.0f; }
    if (t.z > 0.0f) { float d = t.z - p.z; s = fmaf(d, d, s); c += 1.0f; }
    if (t.w > 0.0f) { float d = t.w - p.w; s = fmaf(d, d, s); c += 1.0f; }
}

__global__ void __launch_bounds__(NTHR) el_tma_kernel(
    const float* __restrict__ pred,
    const float* __restrict__ targ,
    float* __restrict__ out,
    int n)
{
    __shared__ __align__(128) float s_t[STAGES][CHUNK];
    __shared__ __align__(128) float s_p[STAGES][CHUNK];
    __shared__ __align__(8)  uint64_t s_mbar[STAGES];

    const int tid = threadIdx.x;
    const int bid = blockIdx.x;
    const int nchunks = n / CHUNK;
    // chunks for this CTA: bid, bid+GRID, bid+2*GRID, ...
    const int my_n = (nchunks > bid) ? (nchunks - bid + GRID - 1) / GRID : 0;

    uint32_t mb[STAGES];
    #pragma unroll
    for (int s = 0; s < STAGES; s++) mb[s] = smem_u32(&s_mbar[s]);

    if (tid == 0) {
        #pragma unroll
        for (int s = 0; s < STAGES; s++) mbar_init(mb[s], 1);
        asm volatile("fence.proxy.async.shared::cta;" ::: "memory");
    }
    __syncthreads();

    // Prologue: fill the pipeline.
    if (tid == 0) {
        int pre = (my_n < STAGES) ? my_n : STAGES;
        for (int i = 0; i < pre; i++) {
            long chunk = (long)bid + (long)i * GRID;
            long off = chunk * CHUNK;
            mbar_expect_tx(mb[i], 2 * CHUNK * 4);
            bulk_ld(smem_u32(&s_t[i][0]), targ + off, CHUNK * 4, mb[i]);
            bulk_ld(smem_u32(&s_p[i][0]), pred + off, CHUNK * 4, mb[i]);
        }
    }

    float s = 0.0f, c = 0.0f;
    for (int i = 0; i < my_n; i++) {
        int slot  = i % STAGES;
        int phase = (i / STAGES) & 1;
        mbar_wait(mb[slot], phase);

        const float4* tt = (const float4*)&s_t[slot][0];
        const float4* pp = (const float4*)&s_p[slot][0];
        // CHUNK/4 = 256 float4 -> exactly 1 per thread
        float4 t = tt[tid];
        float4 p = pp[tid];
        acc4(t, p, s, c);

        __syncthreads();  // everyone done reading this slot
        if (tid == 0 && i + STAGES < my_n) {
            long chunk = (long)bid + (long)(i + STAGES) * GRID;
            long off = chunk * CHUNK;
            mbar_expect_tx(mb[slot], 2 * CHUNK * 4);
            bulk_ld(smem_u32(&s_t[slot][0]), targ + off, CHUNK * 4, mb[slot]);
            bulk_ld(smem_u32(&s_p[slot][0]), pred + off, CHUNK * 4, mb[slot]);
        }
    }

    // Remainder elements (n not multiple of CHUNK; none for 4096x4096).
    for (int idx = nchunks * CHUNK + bid * NTHR + tid; idx < n; idx += GRID * NTHR) {
        float t = targ[idx], p = pred[idx];
        if (t > 0.0f) { float d = t - p; s = fmaf(d, d, s); c += 1.0f; }
    }

    // intra-block reduce
    #pragma unroll
    for (int o = 16; o > 0; o >>= 1) {
        s += __shfl_down_sync(0xFFFFFFFFu, s, o);
        c += __shfl_down_sync(0xFFFFFFFFu, c, o);
    }
    __shared__ float ss[8], sc[8];
    int lane = tid & 31;
    int wid  = tid >> 5;
    if (lane == 0) { ss[wid] = s; sc[wid] = c; }
    __syncthreads();
    if (wid == 0) {
        s = (lane < (NTHR >> 5)) ? ss[lane] : 0.0f;
        c = (lane < (NTHR >> 5)) ? sc[lane] : 0.0f;
        #pragma unroll
        for (int o = 4; o > 0; o >>= 1) {
            s += __shfl_down_sync(0xFFFFFFFFu, s, o);
            c += __shfl_down_sync(0xFFFFFFFFu, c, o);
        }
    }

    // publish partial, take self-resetting ticket
    __shared__ bool is_last;
    if (tid == 0) {
        g_partials[bid] = make_float2(s, c);
        __threadfence();
        unsigned int ticket = atomicInc(&g_ticket, GRID - 1);
        is_last = (ticket == GRID - 1);
    }
    __syncthreads();
    if (!is_last) return;

    // ---- last block: fold partials in fp64, finalize ----
    double ds = 0.0, dc = 0.0;
    for (int k = tid; k < GRID; k += NTHR) {
        volatile float2* vp = (volatile float2*)&g_partials[k];
        ds += (double)vp->x;
        dc += (double)vp->y;
    }
    #pragma unroll
    for (int o = 16; o > 0; o >>= 1) {
        ds += __shfl_down_sync(0xFFFFFFFFu, ds, o);
        dc += __shfl_down_sync(0xFFFFFFFFu, dc, o);
    }
    __shared__ double dss[8], dcc[8];
    if (lane == 0) { dss[wid] = ds; dcc[wid] = dc; }
    __syncthreads();
    if (wid == 0) {
        ds = (lane < (NTHR >> 5)) ? dss[lane] : 0.0;
        dc = (lane < (NTHR >> 5)) ? dcc[lane] : 0.0;
        #pragma unroll
        for (int o = 4; o > 0; o >>= 1) {
            ds += __shfl_down_sync(0xFFFFFFFFu, ds, o);
            dc += __shfl_down_sync(0xFFFFFFFFu, dc, o);
        }
        if (lane == 0) {
            const int    idx[6] = {0, 1, 2, H_DIM - 3, H_DIM - 2, H_DIM - 1};
            const double w[6]   = {-0.75, -1.0, -0.25, 0.25, 1.0, 0.75};
            double corner = 0.0;
            #pragma unroll
            for (int a = 0; a < 6; a++) {
                #pragma unroll
                for (int b = 0; b < 6; b++) {
                    long off = (long)idx[a] * W_DIM + idx[b];
                    double d = (double)__ldg(targ + off) - (double)__ldg(pred + off);
                    corner += d * w[a] * w[b];
                }
            }
            double cnt = (dc < 1.0) ? 1.0 : dc;
            double mse = ds / cnt;
            double N   = (double)H_DIM * (double)W_DIM;
            out[0] = (float)(ALPHA * (corner / N) + (1.0 - ALPHA) * mse);
        }
    }
}

extern "C" void kernel_launch(void* const* d_in, const int* in_sizes, int n_in,
                              void* d_out, int out_size) {
    const float* pred = (const float*)d_in[0];
    const float* targ = (const float*)d_in[1];
    float* out = (float*)d_out;
    int n = in_sizes[0];

    el_tma_kernel<<<GRID, NTHR>>>(pred, targ, out, n);
}